// round 1
// baseline (speedup 1.0000x reference)
#include <cuda_runtime.h>

#define GS     16
#define NPAIR  136          // 16*17/2 lower-triangular pairs
#define NACC   152          // 136 pair sums + 16 channel sums
#define GROUPS 32
#define BATCH  32
#define HW     3136         // 56*56
#define HW4    784          // HW/4
#define CH     512

static __device__ float d_acc[GROUPS][NACC];   // pair sums + channel sums
static __device__ float d_Linv[GROUPS][NPAIR]; // packed lower-triangular Linv
static __device__ float d_bias[CH];            // Linv @ mean, per channel

// ---------------------------------------------------------------------------
__global__ void zero_kernel() {
    int i = blockIdx.x * blockDim.x + threadIdx.x;
    if (i < GROUPS * NACC) ((float*)d_acc)[i] = 0.f;
}

// ---------------------------------------------------------------------------
// Stats: one block per (batch, group). Each thread accumulates 136 pair
// products + 16 sums over its strided spatial positions, then warp-shuffle
// reduce -> smem reduce -> one atomicAdd per value per block.
__global__ void __launch_bounds__(256, 1) stats_kernel(const float* __restrict__ x) {
    const int g = blockIdx.x & 31;
    const int b = blockIdx.x >> 5;
    const float* base = x + ((size_t)b * CH + (size_t)g * GS) * HW;

    float acc[NACC];
#pragma unroll
    for (int k = 0; k < NACC; k++) acc[k] = 0.f;

    for (int pos = threadIdx.x; pos < HW; pos += 256) {
        float v[GS];
#pragma unroll
        for (int c = 0; c < GS; c++) v[c] = __ldg(base + (size_t)c * HW + pos);
#pragma unroll
        for (int i = 0; i < GS; i++) {
#pragma unroll
            for (int j = 0; j <= i; j++)
                acc[i * (i + 1) / 2 + j] = fmaf(v[i], v[j], acc[i * (i + 1) / 2 + j]);
            acc[NPAIR + i] += v[i];
        }
    }

    // intra-warp butterfly reduction of all 152 accumulators
#pragma unroll
    for (int k = 0; k < NACC; k++) {
#pragma unroll
        for (int off = 16; off > 0; off >>= 1)
            acc[k] += __shfl_xor_sync(0xffffffffu, acc[k], off);
    }

    __shared__ float red[8][NACC];
    const int warp = threadIdx.x >> 5, lane = threadIdx.x & 31;
    if (lane == 0) {
#pragma unroll
        for (int k = 0; k < NACC; k++) red[warp][k] = acc[k];
    }
    __syncthreads();

    if (threadIdx.x < NACC) {
        float s = 0.f;
#pragma unroll
        for (int w = 0; w < 8; w++) s += red[w][threadIdx.x];
        atomicAdd(&d_acc[g][threadIdx.x], s);
    }
}

// ---------------------------------------------------------------------------
// Per-group 16x16: cov -> shrink -> Cholesky -> inverse of L -> bias. fp64.
__global__ void solve_kernel() {
    const int g = threadIdx.x;
    if (g >= GROUPS) return;
    const double Nd   = (double)BATCH * (double)HW;
    const double EPSd = 1e-3;

    double m[GS];
#pragma unroll
    for (int i = 0; i < GS; i++) m[i] = (double)d_acc[g][NPAIR + i] / Nd;

    double P[GS][GS];
    for (int i = 0; i < GS; i++)
        for (int j = 0; j <= i; j++) {
            double c = (double)d_acc[g][i * (i + 1) / 2 + j] / Nd - m[i] * m[j];
            c *= (1.0 - EPSd);
            if (i == j) c += EPSd;
            P[i][j] = c;
        }

    double L[GS][GS];
    for (int j = 0; j < GS; j++) {
        double s = P[j][j];
        for (int k = 0; k < j; k++) s -= L[j][k] * L[j][k];
        double ljj = sqrt(s);
        L[j][j] = ljj;
        for (int i = j + 1; i < GS; i++) {
            double t = P[i][j];
            for (int k = 0; k < j; k++) t -= L[i][k] * L[j][k];
            L[i][j] = t / ljj;
        }
    }

    double inv[GS][GS];
    for (int j = 0; j < GS; j++) {
        inv[j][j] = 1.0 / L[j][j];
        for (int i = j + 1; i < GS; i++) {
            double t = 0.0;
            for (int k = j; k < i; k++) t += L[i][k] * inv[k][j];
            inv[i][j] = -t / L[i][i];
        }
    }

    for (int i = 0; i < GS; i++) {
        double bsum = 0.0;
        for (int j = 0; j <= i; j++) {
            d_Linv[g][i * (i + 1) / 2 + j] = (float)inv[i][j];
            bsum += inv[i][j] * m[j];
        }
        d_bias[g * GS + i] = (float)bsum;
    }
}

// ---------------------------------------------------------------------------
// Apply: out_i = sum_{j<=i} Linv_ij * x_j - bias_i, vectorized float4 over hw.
__global__ void __launch_bounds__(256) apply_kernel(const float* __restrict__ x,
                                                    float* __restrict__ out) {
    const int g = blockIdx.x & 31;
    const int b = blockIdx.x >> 5;

    __shared__ float Ls[NPAIR];
    __shared__ float bs[GS];
    if (threadIdx.x < NPAIR) Ls[threadIdx.x] = d_Linv[g][threadIdx.x];
    if (threadIdx.x < GS)    bs[threadIdx.x] = d_bias[g * GS + threadIdx.x];
    __syncthreads();

    const size_t off = ((size_t)b * CH + (size_t)g * GS) * HW;
    const float4* in = (const float4*)(x + off);
    float4*       op = (float4*)(out + off);

    for (int pos = threadIdx.x; pos < HW4; pos += 256) {
        float4 v[GS];
#pragma unroll
        for (int c = 0; c < GS; c++) v[c] = in[(size_t)c * HW4 + pos];
#pragma unroll
        for (int i = 0; i < GS; i++) {
            const float bias = bs[i];
            float4 a;
            a.x = -bias; a.y = -bias; a.z = -bias; a.w = -bias;
#pragma unroll
            for (int j = 0; j <= i; j++) {
                const float f = Ls[i * (i + 1) / 2 + j];
                a.x = fmaf(f, v[j].x, a.x);
                a.y = fmaf(f, v[j].y, a.y);
                a.z = fmaf(f, v[j].z, a.z);
                a.w = fmaf(f, v[j].w, a.w);
            }
            op[(size_t)i * HW4 + pos] = a;
        }
    }
}

// ---------------------------------------------------------------------------
extern "C" void kernel_launch(void* const* d_in, const int* in_sizes, int n_in,
                              void* d_out, int out_size) {
    const float* x   = (const float*)d_in[0];
    float*       out = (float*)d_out;

    zero_kernel<<<(GROUPS * NACC + 255) / 256, 256>>>();
    stats_kernel<<<GROUPS * BATCH, 256>>>(x);
    solve_kernel<<<1, 32>>>();
    apply_kernel<<<GROUPS * BATCH, 256>>>(x, out);
}